// round 6
// baseline (speedup 1.0000x reference)
#include <cuda_runtime.h>
#include <cstdint>
#include <cstddef>

// ---------------- problem dims (fixed) ----------------
#define I_DIM   4
#define H_DIM   2048
#define O_DIM   2
#define R_DIM   2
#define S_DIM   2
#define GB_DIM  8
#define B_DIM   32
#define T_DIM   1024
#define ALPHA_C 0.2f
#define SIGMA_C 0.05f

#define NTHREADS 512
#define EPT      4          // neurons per thread: 512*4 = 2048
#define NWARPS   (NTHREADS / 32)   // 16

typedef unsigned long long u64;

// ---------------- precomputed proxy weights (device scratch) ----------------
__device__ __align__(16) float g_wi[I_DIM * H_DIM];  // alpha * wi,   layout [i][h]
__device__ __align__(16) float g_m [R_DIM * H_DIM];  // (alpha/H)*m,  layout [r][h]
__device__ __align__(16) float g_n [R_DIM * H_DIM];  // n (raw),      layout [r][h]
__device__ __align__(16) float g_wo[O_DIM * H_DIM];  // wo / H,       layout [o][h]
__device__ __align__(16) float g_h0[H_DIM];

// ---------------- packed f32x2 helpers (sm_103a) ----------------
__device__ __forceinline__ u64 pack2(float lo, float hi) {
    u64 r; asm("mov.b64 %0, {%1, %2};" : "=l"(r) : "f"(lo), "f"(hi)); return r;
}
__device__ __forceinline__ u64 dup2(float x) { return pack2(x, x); }
__device__ __forceinline__ void unpack2(u64 v, float& lo, float& hi) {
    asm("mov.b64 {%0, %1}, %2;" : "=f"(lo), "=f"(hi) : "l"(v));
}
__device__ __forceinline__ u64 fma2(u64 a, u64 b, u64 c) {
    u64 d; asm("fma.rn.f32x2 %0, %1, %2, %3;" : "=l"(d) : "l"(a), "l"(b), "l"(c)); return d;
}
__device__ __forceinline__ u64 mul2(u64 a, u64 b) {
    u64 d; asm("mul.rn.f32x2 %0, %1, %2;" : "=l"(d) : "l"(a), "l"(b)); return d;
}
__device__ __forceinline__ u64 add2(u64 a, u64 b) {
    u64 d; asm("add.rn.f32x2 %0, %1, %2;" : "=l"(d) : "l"(a), "l"(b)); return d;
}
// HW tanh approximation (single MUFU op).
__device__ __forceinline__ float tanh_hw(float x) {
    float y; asm("tanh.approx.f32 %0, %1;" : "=f"(y) : "f"(x)); return y;
}

// sum NW (p0,p1) pairs stored as 2*NW consecutive floats: NW/2 LDS.128 + (NW-1) add2
__device__ __forceinline__ u64 sum_pairs16(const float* buf) {
    const ulonglong2* pb2 = reinterpret_cast<const ulonglong2*>(buf);
    ulonglong2 v0 = pb2[0], v1 = pb2[1], v2 = pb2[2], v3 = pb2[3];
    ulonglong2 v4 = pb2[4], v5 = pb2[5], v6 = pb2[6], v7 = pb2[7];
    u64 s0 = add2(add2(v0.x, v0.y), add2(v1.x, v1.y));
    u64 s1 = add2(add2(v2.x, v2.y), add2(v3.x, v3.y));
    u64 s2 = add2(add2(v4.x, v4.y), add2(v5.x, v5.y));
    u64 s3 = add2(add2(v6.x, v6.y), add2(v7.x, v7.y));
    return add2(add2(s0, s1), add2(s2, s3));
}

// 4-value interleaved warp reduction: 9 SHFL total.
// Returns d where lane L holds the full-warp sum of class (L&3):
//   class 0 -> a0, 1 -> a1, 2 -> a2, 3 -> a3.
__device__ __forceinline__ float warp_reduce4(float a0, float a1, float a2, float a3,
                                              int lane) {
    float t0 = __shfl_xor_sync(0xffffffffu, a0, 1);
    float t1 = __shfl_xor_sync(0xffffffffu, a1, 1);
    float t2 = __shfl_xor_sync(0xffffffffu, a2, 1);
    float t3 = __shfl_xor_sync(0xffffffffu, a3, 1);
    float c0 = (lane & 1) ? (a1 + t1) : (a0 + t0);
    float c1 = (lane & 1) ? (a3 + t3) : (a2 + t2);
    float u0 = __shfl_xor_sync(0xffffffffu, c0, 2);
    float u1 = __shfl_xor_sync(0xffffffffu, c1, 2);
    float d  = (lane & 2) ? (c1 + u1) : (c0 + u0);
    d += __shfl_xor_sync(0xffffffffu, d, 4);
    d += __shfl_xor_sync(0xffffffffu, d, 8);
    d += __shfl_xor_sync(0xffffffffu, d, 16);
    return d;
}

// ---------------- kernel 1: build proxies ----------------
__global__ void proxy_kernel(
    const float* __restrict__ gb, const float* __restrict__ sup,
    const float* __restrict__ wi_w, const float* __restrict__ m_w,
    const float* __restrict__ n_w, const float* __restrict__ wo_w,
    const float* __restrict__ wi_b, const float* __restrict__ m_b,
    const float* __restrict__ n_b, const float* __restrict__ h0_w)
{
    int h = blockIdx.x * blockDim.x + threadIdx.x;
    if (h >= H_DIM) return;

    float gbh[GB_DIM];
#pragma unroll
    for (int g = 0; g < GB_DIM; ++g) gbh[g] = gb[g * H_DIM + h];
    float sv[S_DIM];
#pragma unroll
    for (int s = 0; s < S_DIM; ++s) sv[s] = sup[s * H_DIM + h];

#pragma unroll
    for (int i = 0; i < I_DIM; ++i) {
        float acc = 0.f;
#pragma unroll
        for (int s = 0; s < S_DIM; ++s) {
            float d = 0.f;
#pragma unroll
            for (int g = 0; g < GB_DIM; ++g)
                d = fmaf(wi_w[(i * S_DIM + s) * GB_DIM + g], gbh[g], d);
            acc = fmaf(sv[s], d, acc);
            acc = fmaf(wi_b[i * S_DIM + s], sv[s], acc);
        }
        g_wi[i * H_DIM + h] = ALPHA_C * acc;
    }

#pragma unroll
    for (int r = 0; r < R_DIM; ++r) {
        float am = 0.f, an = 0.f;
#pragma unroll
        for (int s = 0; s < S_DIM; ++s) {
            float dm = 0.f, dn = 0.f;
#pragma unroll
            for (int g = 0; g < GB_DIM; ++g) {
                dm = fmaf(m_w[(r * S_DIM + s) * GB_DIM + g], gbh[g], dm);
                dn = fmaf(n_w[(r * S_DIM + s) * GB_DIM + g], gbh[g], dn);
            }
            am = fmaf(sv[s], dm, am);
            am = fmaf(m_b[r * S_DIM + s], sv[s], am);
            an = fmaf(sv[s], dn, an);
            an = fmaf(n_b[r * S_DIM + s], sv[s], an);
        }
        g_m[r * H_DIM + h] = (ALPHA_C / (float)H_DIM) * am;
        g_n[r * H_DIM + h] = an;
    }

#pragma unroll
    for (int o = 0; o < O_DIM; ++o) {
        float ao = 0.f;
#pragma unroll
        for (int s = 0; s < S_DIM; ++s) {
            float d = 0.f;
#pragma unroll
            for (int g = 0; g < GB_DIM; ++g)
                d = fmaf(wo_w[(o * S_DIM + s) * GB_DIM + g], gbh[g], d);
            ao = fmaf(sv[s], d, ao);
        }
        g_wo[o * H_DIM + h] = ao * (1.0f / (float)H_DIM);
    }

    {
        float ah = 0.f;
#pragma unroll
        for (int s = 0; s < S_DIM; ++s) {
            float d = 0.f;
#pragma unroll
            for (int g = 0; g < GB_DIM; ++g)
                d = fmaf(h0_w[s * GB_DIM + g], gbh[g], d);
            ah = fmaf(sv[s], d, ah);
        }
        g_h0[h] = ah;
    }
}

// ---------------- kernel 2: fused sequential RNN scan (traj + out) ----------------
__global__ void __launch_bounds__(NTHREADS, 1)
rnn_kernel(const float* __restrict__ input,   // (B, T, I)
           const float* __restrict__ noise,   // (B, T, H)
           float* __restrict__ out,           // (B, T, O)
           float* __restrict__ traj)          // (B, T, H)
{
    const int b    = blockIdx.x;
    const int tid  = threadIdx.x;
    const int lane = tid & 31;
    const int wid  = tid >> 5;
    const int j0   = tid * EPT;

    // double-buffered per-warp partials (16 warps -> 32 floats each)
    __shared__ __align__(16) float pbuf[2][NWARPS * 2];  // (p0,p1) per warp
    __shared__ __align__(16) float qbuf[2][NWARPS * 2];  // (q0,q1) per warp

    // --- load per-element weights, packed: pairs (e0,e1),(e2,e3) ---
    u64 wi_p[I_DIM][2];
#pragma unroll
    for (int i = 0; i < I_DIM; ++i) {
        float4 v = *reinterpret_cast<const float4*>(&g_wi[i * H_DIM + j0]);
        wi_p[i][0] = pack2(v.x, v.y);
        wi_p[i][1] = pack2(v.z, v.w);
    }
    u64 m0_p[2], m1_p[2];
    {
        float4 v = *reinterpret_cast<const float4*>(&g_m[0 * H_DIM + j0]);
        m0_p[0] = pack2(v.x, v.y); m0_p[1] = pack2(v.z, v.w);
        v = *reinterpret_cast<const float4*>(&g_m[1 * H_DIM + j0]);
        m1_p[0] = pack2(v.x, v.y); m1_p[1] = pack2(v.z, v.w);
    }
    // per element e: (n0[e],n1[e]) and (wo0[e],wo1[e]) packed
    u64 n01_p[EPT], wo01_p[EPT];
    {
        float4 a = *reinterpret_cast<const float4*>(&g_n[0 * H_DIM + j0]);
        float4 c = *reinterpret_cast<const float4*>(&g_n[1 * H_DIM + j0]);
        n01_p[0] = pack2(a.x, c.x); n01_p[1] = pack2(a.y, c.y);
        n01_p[2] = pack2(a.z, c.z); n01_p[3] = pack2(a.w, c.w);
        a = *reinterpret_cast<const float4*>(&g_wo[0 * H_DIM + j0]);
        c = *reinterpret_cast<const float4*>(&g_wo[1 * H_DIM + j0]);
        wo01_p[0] = pack2(a.x, c.x); wo01_p[1] = pack2(a.y, c.y);
        wo01_p[2] = pack2(a.z, c.z); wo01_p[3] = pack2(a.w, c.w);
    }

    const u64 SIG2 = dup2(SIGMA_C);
    const u64 C08  = dup2(1.0f - ALPHA_C);

    // --- state: 2 packed pairs + 4 tanh values ---
    u64 h_p[2];
    float r[EPT];
    {
        float4 v = *reinterpret_cast<const float4*>(&g_h0[j0]);
        h_p[0] = pack2(v.x, v.y);
        h_p[1] = pack2(v.z, v.w);
        r[0] = tanh_hw(v.x); r[1] = tanh_hw(v.y);
        r[2] = tanh_hw(v.z); r[3] = tanh_hw(v.w);
    }

    const float* nrow = noise + ((size_t)b * T_DIM) * H_DIM + j0;
    const float* irow = input + (size_t)b * T_DIM * I_DIM;
    float*       trow = traj  + ((size_t)b * T_DIM) * H_DIM + j0;
    float*       orow = out   + (size_t)b * T_DIM * O_DIM;

    // prefetch pipeline: depth 2 (covers DRAM latency over ~300cyc steps)
    ulonglong2 nz0 = __ldg(reinterpret_cast<const ulonglong2*>(nrow));
    float4     iv0 = __ldg(reinterpret_cast<const float4*>(irow));
    ulonglong2 nz1 = __ldg(reinterpret_cast<const ulonglong2*>(nrow + (size_t)1 * H_DIM));
    float4     iv1 = __ldg(reinterpret_cast<const float4*>(irow + 1 * I_DIM));

    __syncthreads();

    for (int t = 0; t < T_DIM; ++t) {
        const int buf = t & 1;

        // prefetch t+2
        ulonglong2 nz2 = nz1; float4 iv2 = iv1;
        if (t + 2 < T_DIM) {
            nz2 = __ldg(reinterpret_cast<const ulonglong2*>(nrow + (size_t)(t + 2) * H_DIM));
            iv2 = __ldg(reinterpret_cast<const float4*>(irow + (size_t)(t + 2) * I_DIM));
        }

        // packed dots with r = tanh(h_{t-1}):
        //   pacc = (Σ r n0, Σ r n1)   qacc = (Σ r wo0, Σ r wo1)
        u64 rd0 = dup2(r[0]), rd1 = dup2(r[1]), rd2 = dup2(r[2]), rd3 = dup2(r[3]);
        u64 pa = mul2(rd0, n01_p[0]);
        u64 pb = mul2(rd1, n01_p[1]);
        u64 qa = mul2(rd0, wo01_p[0]);
        u64 qb = mul2(rd1, wo01_p[1]);
        pa = fma2(rd2, n01_p[2], pa);
        pb = fma2(rd3, n01_p[3], pb);
        qa = fma2(rd2, wo01_p[2], qa);
        qb = fma2(rd3, wo01_p[3], qb);
        u64 pacc = add2(pa, pb);
        u64 qacc = add2(qa, qb);

        // 9-SHFL interleaved warp reduce of (p0,p1,q0,q1)
        float a0, a1, a2, a3;
        unpack2(pacc, a0, a1);
        unpack2(qacc, a2, a3);
        float d = warp_reduce4(a0, a1, a2, a3, lane);

        // lanes 0,1 hold p0,p1; lanes 2,3 hold q0,q1
        if (lane < 2)           pbuf[buf][wid * 2 + lane]       = d;
        else if (lane < 4)      qbuf[buf][wid * 2 + (lane - 2)] = d;
        __syncthreads();

        // every thread sums ALL 16 warp (p0,p1) pairs: 8x LDS.128 + 15 add2
        u64 P = sum_pairs16(&pbuf[buf][0]);
        float fp0, fp1; unpack2(P, fp0, fp1);
        const u64 P0 = dup2(fp0), P1 = dup2(fp1);

        // thread 0: finish q reduce (off critical path) -> output of step t-1
        if (tid == 0 && t > 0) {
            u64 Q = sum_pairs16(&qbuf[buf][0]);
            float fq0, fq1; unpack2(Q, fq0, fq1);
            *reinterpret_cast<float2*>(&orow[(t - 1) * O_DIM]) = make_float2(fq0, fq1);
        }

        // h update, packed pairs
        const u64 ivx = dup2(iv0.x), ivy = dup2(iv0.y), ivz = dup2(iv0.z), ivw = dup2(iv0.w);
        const u64 nzp[2] = {nz0.x, nz0.y};
#pragma unroll
        for (int k = 0; k < 2; ++k) {
            u64 u = mul2(ivw, wi_p[3][k]);
            u = fma2(ivz, wi_p[2][k], u);
            u = fma2(ivy, wi_p[1][k], u);
            u = fma2(ivx, wi_p[0][k], u);
            u = fma2(nzp[k], SIG2, u);
            u = fma2(P0, m0_p[k], u);
            u = fma2(P1, m1_p[k], u);
            h_p[k] = fma2(h_p[k], C08, u);
        }

        // tanh for next step
        {
            float x0, x1, x2, x3;
            unpack2(h_p[0], x0, x1);
            unpack2(h_p[1], x2, x3);
            r[0] = tanh_hw(x0); r[1] = tanh_hw(x1);
            r[2] = tanh_hw(x2); r[3] = tanh_hw(x3);
        }

        // store trajectory (h): 1x STG.128
        {
            ulonglong2 st; st.x = h_p[0]; st.y = h_p[1];
            *reinterpret_cast<ulonglong2*>(trow + (size_t)t * H_DIM) = st;
        }

        // rotate prefetch pipeline
        nz0 = nz1; iv0 = iv1;
        nz1 = nz2; iv1 = iv2;
    }

    // final output row (t = T-1) from the last tanh(h)
    {
        u64 qa = mul2(dup2(r[0]), wo01_p[0]);
        u64 qb = mul2(dup2(r[1]), wo01_p[1]);
        qa = fma2(dup2(r[2]), wo01_p[2], qa);
        qb = fma2(dup2(r[3]), wo01_p[3], qb);
        u64 qacc = add2(qa, qb);
        float a0, a1; unpack2(qacc, a0, a1);
        float d = warp_reduce4(a0, a1, 0.f, 0.f, lane);
        if (lane < 2) qbuf[0][wid * 2 + lane] = d;
        __syncthreads();
        if (tid == 0) {
            u64 Q = sum_pairs16(&qbuf[0][0]);
            float fq0, fq1; unpack2(Q, fq0, fq1);
            *reinterpret_cast<float2*>(&orow[(T_DIM - 1) * O_DIM]) = make_float2(fq0, fq1);
        }
    }
}

// ---------------- launcher ----------------
extern "C" void kernel_launch(void* const* d_in, const int* in_sizes, int n_in,
                              void* d_out, int out_size) {
    const float* input = (const float*)d_in[0];   // (B,T,I)
    const float* noise = (const float*)d_in[1];   // (B,T,H)
    const float* gb    = (const float*)d_in[2];   // (GB,H)
    const float* sup   = (const float*)d_in[3];   // (S,H)
    const float* wi_w  = (const float*)d_in[4];   // (I,S,GB)
    const float* m_w   = (const float*)d_in[5];   // (R,S,GB)
    const float* n_w   = (const float*)d_in[6];   // (R,S,GB)
    const float* wo_w  = (const float*)d_in[7];   // (O,S,GB)
    const float* wi_b  = (const float*)d_in[8];   // (I,S)
    const float* m_b   = (const float*)d_in[9];   // (R,S)
    const float* n_b   = (const float*)d_in[10];  // (R,S)
    const float* h0_w  = (const float*)d_in[11];  // (S,GB)

    float* out  = (float*)d_out;                                   // (B,T,O)
    float* traj = (float*)d_out + (size_t)B_DIM * T_DIM * O_DIM;   // (B,T,H)

    proxy_kernel<<<(H_DIM + 255) / 256, 256>>>(gb, sup, wi_w, m_w, n_w, wo_w,
                                               wi_b, m_b, n_b, h0_w);
    rnn_kernel<<<B_DIM, NTHREADS>>>(input, noise, out, traj);
}

// round 7
// speedup vs baseline: 1.0900x; 1.0900x over previous
#include <cuda_runtime.h>
#include <cstdint>
#include <cstddef>

// ---------------- problem dims (fixed) ----------------
#define I_DIM   4
#define H_DIM   2048
#define O_DIM   2
#define R_DIM   2
#define S_DIM   2
#define GB_DIM  8
#define B_DIM   32
#define T_DIM   1024
#define ALPHA_C 0.2f
#define SIGMA_C 0.05f

#define NTHREADS 512
#define EPT      4          // neurons per thread: 512*4 = 2048
#define NWARPS   (NTHREADS / 32)   // 16

typedef unsigned long long u64;

// ---------------- precomputed proxy weights (device scratch) ----------------
__device__ __align__(16) float g_wi[I_DIM * H_DIM];  // alpha * wi,   layout [i][h]
__device__ __align__(16) float g_m [R_DIM * H_DIM];  // (alpha/H)*m,  layout [r][h]
__device__ __align__(16) float g_n [R_DIM * H_DIM];  // n (raw),      layout [r][h]
__device__ __align__(16) float g_wo[O_DIM * H_DIM];  // wo / H,       layout [o][h]
__device__ __align__(16) float g_h0[H_DIM];

// ---------------- packed f32x2 helpers (sm_103a) ----------------
__device__ __forceinline__ u64 pack2(float lo, float hi) {
    u64 r; asm("mov.b64 %0, {%1, %2};" : "=l"(r) : "f"(lo), "f"(hi)); return r;
}
__device__ __forceinline__ u64 dup2(float x) { return pack2(x, x); }
__device__ __forceinline__ void unpack2(u64 v, float& lo, float& hi) {
    asm("mov.b64 {%0, %1}, %2;" : "=f"(lo), "=f"(hi) : "l"(v));
}
__device__ __forceinline__ u64 fma2(u64 a, u64 b, u64 c) {
    u64 d; asm("fma.rn.f32x2 %0, %1, %2, %3;" : "=l"(d) : "l"(a), "l"(b), "l"(c)); return d;
}
__device__ __forceinline__ u64 mul2(u64 a, u64 b) {
    u64 d; asm("mul.rn.f32x2 %0, %1, %2;" : "=l"(d) : "l"(a), "l"(b)); return d;
}
__device__ __forceinline__ u64 add2(u64 a, u64 b) {
    u64 d; asm("add.rn.f32x2 %0, %1, %2;" : "=l"(d) : "l"(a), "l"(b)); return d;
}
// HW tanh approximation (single MUFU op).
__device__ __forceinline__ float tanh_hw(float x) {
    float y; asm("tanh.approx.f32 %0, %1;" : "=f"(y) : "f"(x)); return y;
}

// 4-value interleaved warp reduction: 9 SHFL total.
// Returns d where lane L holds the full-warp sum of class (L&3):
//   class 0 -> a0, 1 -> a1, 2 -> a2, 3 -> a3.
__device__ __forceinline__ float warp_reduce4(float a0, float a1, float a2, float a3,
                                              int lane) {
    float t0 = __shfl_xor_sync(0xffffffffu, a0, 1);
    float t1 = __shfl_xor_sync(0xffffffffu, a1, 1);
    float t2 = __shfl_xor_sync(0xffffffffu, a2, 1);
    float t3 = __shfl_xor_sync(0xffffffffu, a3, 1);
    float c0 = (lane & 1) ? (a1 + t1) : (a0 + t0);
    float c1 = (lane & 1) ? (a3 + t3) : (a2 + t2);
    float u0 = __shfl_xor_sync(0xffffffffu, c0, 2);
    float u1 = __shfl_xor_sync(0xffffffffu, c1, 2);
    float d  = (lane & 2) ? (c1 + u1) : (c0 + u0);
    d += __shfl_xor_sync(0xffffffffu, d, 4);
    d += __shfl_xor_sync(0xffffffffu, d, 8);
    d += __shfl_xor_sync(0xffffffffu, d, 16);
    return d;
}

// sum within 16-lane halves: lane0 holds sum of lanes 0..15, lane16 of 16..31
__device__ __forceinline__ float half_reduce16(float v) {
    v += __shfl_xor_sync(0xffffffffu, v, 1);
    v += __shfl_xor_sync(0xffffffffu, v, 2);
    v += __shfl_xor_sync(0xffffffffu, v, 4);
    v += __shfl_xor_sync(0xffffffffu, v, 8);
    return v;
}

// ---------------- kernel 1: build proxies ----------------
__global__ void proxy_kernel(
    const float* __restrict__ gb, const float* __restrict__ sup,
    const float* __restrict__ wi_w, const float* __restrict__ m_w,
    const float* __restrict__ n_w, const float* __restrict__ wo_w,
    const float* __restrict__ wi_b, const float* __restrict__ m_b,
    const float* __restrict__ n_b, const float* __restrict__ h0_w)
{
    int h = blockIdx.x * blockDim.x + threadIdx.x;
    if (h >= H_DIM) return;

    float gbh[GB_DIM];
#pragma unroll
    for (int g = 0; g < GB_DIM; ++g) gbh[g] = gb[g * H_DIM + h];
    float sv[S_DIM];
#pragma unroll
    for (int s = 0; s < S_DIM; ++s) sv[s] = sup[s * H_DIM + h];

#pragma unroll
    for (int i = 0; i < I_DIM; ++i) {
        float acc = 0.f;
#pragma unroll
        for (int s = 0; s < S_DIM; ++s) {
            float d = 0.f;
#pragma unroll
            for (int g = 0; g < GB_DIM; ++g)
                d = fmaf(wi_w[(i * S_DIM + s) * GB_DIM + g], gbh[g], d);
            acc = fmaf(sv[s], d, acc);
            acc = fmaf(wi_b[i * S_DIM + s], sv[s], acc);
        }
        g_wi[i * H_DIM + h] = ALPHA_C * acc;
    }

#pragma unroll
    for (int r = 0; r < R_DIM; ++r) {
        float am = 0.f, an = 0.f;
#pragma unroll
        for (int s = 0; s < S_DIM; ++s) {
            float dm = 0.f, dn = 0.f;
#pragma unroll
            for (int g = 0; g < GB_DIM; ++g) {
                dm = fmaf(m_w[(r * S_DIM + s) * GB_DIM + g], gbh[g], dm);
                dn = fmaf(n_w[(r * S_DIM + s) * GB_DIM + g], gbh[g], dn);
            }
            am = fmaf(sv[s], dm, am);
            am = fmaf(m_b[r * S_DIM + s], sv[s], am);
            an = fmaf(sv[s], dn, an);
            an = fmaf(n_b[r * S_DIM + s], sv[s], an);
        }
        g_m[r * H_DIM + h] = (ALPHA_C / (float)H_DIM) * am;
        g_n[r * H_DIM + h] = an;
    }

#pragma unroll
    for (int o = 0; o < O_DIM; ++o) {
        float ao = 0.f;
#pragma unroll
        for (int s = 0; s < S_DIM; ++s) {
            float d = 0.f;
#pragma unroll
            for (int g = 0; g < GB_DIM; ++g)
                d = fmaf(wo_w[(o * S_DIM + s) * GB_DIM + g], gbh[g], d);
            ao = fmaf(sv[s], d, ao);
        }
        g_wo[o * H_DIM + h] = ao * (1.0f / (float)H_DIM);
    }

    {
        float ah = 0.f;
#pragma unroll
        for (int s = 0; s < S_DIM; ++s) {
            float d = 0.f;
#pragma unroll
            for (int g = 0; g < GB_DIM; ++g)
                d = fmaf(h0_w[s * GB_DIM + g], gbh[g], d);
            ah = fmaf(sv[s], d, ah);
        }
        g_h0[h] = ah;
    }
}

// ---------------- kernel 2: fused sequential RNN scan (traj + out) ----------------
__global__ void __launch_bounds__(NTHREADS, 1)
rnn_kernel(const float* __restrict__ input,   // (B, T, I)
           const float* __restrict__ noise,   // (B, T, H)
           float* __restrict__ out,           // (B, T, O)
           float* __restrict__ traj)          // (B, T, H)
{
    const int b    = blockIdx.x;
    const int tid  = threadIdx.x;
    const int lane = tid & 31;
    const int wid  = tid >> 5;
    const int j0   = tid * EPT;

    // per-warp partials: [0..15]=p0, [16..31]=p1, [32..47]=q0, [48..63]=q1
    __shared__ __align__(16) float pqbuf[64];
    // broadcast: {p0,p0,p1,p1} as one 16B vector
    __shared__ __align__(16) float bc[4];

    // --- load per-element weights, packed: pairs (e0,e1),(e2,e3) ---
    u64 wi_p[I_DIM][2];
#pragma unroll
    for (int i = 0; i < I_DIM; ++i) {
        float4 v = *reinterpret_cast<const float4*>(&g_wi[i * H_DIM + j0]);
        wi_p[i][0] = pack2(v.x, v.y);
        wi_p[i][1] = pack2(v.z, v.w);
    }
    u64 m0_p[2], m1_p[2];
    {
        float4 v = *reinterpret_cast<const float4*>(&g_m[0 * H_DIM + j0]);
        m0_p[0] = pack2(v.x, v.y); m0_p[1] = pack2(v.z, v.w);
        v = *reinterpret_cast<const float4*>(&g_m[1 * H_DIM + j0]);
        m1_p[0] = pack2(v.x, v.y); m1_p[1] = pack2(v.z, v.w);
    }
    // per element e: (n0[e],n1[e]) and (wo0[e],wo1[e]) packed
    u64 n01_p[EPT], wo01_p[EPT];
    {
        float4 a = *reinterpret_cast<const float4*>(&g_n[0 * H_DIM + j0]);
        float4 c = *reinterpret_cast<const float4*>(&g_n[1 * H_DIM + j0]);
        n01_p[0] = pack2(a.x, c.x); n01_p[1] = pack2(a.y, c.y);
        n01_p[2] = pack2(a.z, c.z); n01_p[3] = pack2(a.w, c.w);
        a = *reinterpret_cast<const float4*>(&g_wo[0 * H_DIM + j0]);
        c = *reinterpret_cast<const float4*>(&g_wo[1 * H_DIM + j0]);
        wo01_p[0] = pack2(a.x, c.x); wo01_p[1] = pack2(a.y, c.y);
        wo01_p[2] = pack2(a.z, c.z); wo01_p[3] = pack2(a.w, c.w);
    }

    const u64 SIG2 = dup2(SIGMA_C);
    const u64 C08  = dup2(1.0f - ALPHA_C);

    // --- state: 2 packed pairs + 4 tanh values ---
    u64 h_p[2];
    float r0, r1, r2, r3;
    {
        float4 v = *reinterpret_cast<const float4*>(&g_h0[j0]);
        h_p[0] = pack2(v.x, v.y);
        h_p[1] = pack2(v.z, v.w);
        r0 = tanh_hw(v.x); r1 = tanh_hw(v.y);
        r2 = tanh_hw(v.z); r3 = tanh_hw(v.w);
    }

    const float* nrow = noise + ((size_t)b * T_DIM) * H_DIM + j0;
    const float* irow = input + (size_t)b * T_DIM * I_DIM;
    float*       trow = traj  + ((size_t)b * T_DIM) * H_DIM + j0;
    float*       orow = out   + (size_t)b * T_DIM * O_DIM;

    // prefetch step 0
    ulonglong2 nz = __ldg(reinterpret_cast<const ulonglong2*>(nrow));
    float4     iv = __ldg(reinterpret_cast<const float4*>(irow));

    __syncthreads();

    for (int t = 0; t < T_DIM; ++t) {
        // prefetch t+1
        ulonglong2 nz_n = nz; float4 iv_n = iv;
        if (t + 1 < T_DIM) {
            nz_n = __ldg(reinterpret_cast<const ulonglong2*>(nrow + (size_t)(t + 1) * H_DIM));
            iv_n = __ldg(reinterpret_cast<const float4*>(irow + (size_t)(t + 1) * I_DIM));
        }

        // packed dots with r = tanh(h_{t-1}):
        //   p = (Σ r n0, Σ r n1)   q = (Σ r wo0, Σ r wo1)
        u64 rd0 = dup2(r0), rd1 = dup2(r1), rd2 = dup2(r2), rd3 = dup2(r3);
        u64 pa = mul2(rd0, n01_p[0]);
        u64 pb = mul2(rd1, n01_p[1]);
        u64 qa = mul2(rd0, wo01_p[0]);
        u64 qb = mul2(rd1, wo01_p[1]);
        pa = fma2(rd2, n01_p[2], pa);
        pb = fma2(rd3, n01_p[3], pb);
        qa = fma2(rd2, wo01_p[2], qa);
        qb = fma2(rd3, wo01_p[3], qb);
        u64 pacc = add2(pa, pb);
        u64 qacc = add2(qa, qb);

        // 9-SHFL interleaved warp reduce of (p0,p1,q0,q1); lane L&3 = class sum
        float a0, a1, a2, a3;
        unpack2(pacc, a0, a1);
        unpack2(qacc, a2, a3);
        float d = warp_reduce4(a0, a1, a2, a3, lane);

        // lanes 0..3 write the 4 warp sums: pqbuf[class*16 + wid]
        if (lane < 4) pqbuf[lane * 16 + wid] = d;
        __syncthreads();   // bar1

        // warp 0: final p reduce; warp 1: final q reduce (off critical path)
        if (wid == 0) {
            float v = half_reduce16(pqbuf[lane]);     // lanes 0-15: p0, 16-31: p1
            if (lane == 0)  { bc[0] = v; bc[1] = v; } // {p0,p0,...}
            if (lane == 16) { bc[2] = v; bc[3] = v; } // {...,p1,p1}
        } else if (wid == 1 && t > 0) {
            float v = half_reduce16(pqbuf[32 + lane]); // lanes 0-15: q0, 16-31: q1
            if (lane == 0)  orow[(t - 1) * O_DIM + 0] = v;
            if (lane == 16) orow[(t - 1) * O_DIM + 1] = v;
        }

        // u-part of the update is independent of P: schedules into the barrier shadow
        const u64 ivx = dup2(iv.x), ivy = dup2(iv.y), ivz = dup2(iv.z), ivw = dup2(iv.w);
        u64 u0 = mul2(ivw, wi_p[3][0]);
        u64 u1 = mul2(ivw, wi_p[3][1]);
        u0 = fma2(ivz, wi_p[2][0], u0);
        u1 = fma2(ivz, wi_p[2][1], u1);
        u0 = fma2(ivy, wi_p[1][0], u0);
        u1 = fma2(ivy, wi_p[1][1], u1);
        u0 = fma2(ivx, wi_p[0][0], u0);
        u1 = fma2(ivx, wi_p[0][1], u1);
        u0 = fma2(nz.x, SIG2, u0);
        u1 = fma2(nz.y, SIG2, u1);

        __syncthreads();   // bar2

        // one LDS.128: {P0dup, P1dup}
        ulonglong2 Pv = *reinterpret_cast<const ulonglong2*>(bc);
        const u64 P0 = Pv.x, P1 = Pv.y;

        // finish h update
        u0 = fma2(P0, m0_p[0], u0);
        u1 = fma2(P0, m0_p[1], u1);
        u0 = fma2(P1, m1_p[0], u0);
        u1 = fma2(P1, m1_p[1], u1);
        h_p[0] = fma2(h_p[0], C08, u0);
        h_p[1] = fma2(h_p[1], C08, u1);

        // tanh for next step
        {
            float x0, x1, x2, x3;
            unpack2(h_p[0], x0, x1);
            unpack2(h_p[1], x2, x3);
            r0 = tanh_hw(x0); r1 = tanh_hw(x1);
            r2 = tanh_hw(x2); r3 = tanh_hw(x3);
        }

        // store trajectory (h): 1x STG.128
        {
            ulonglong2 st; st.x = h_p[0]; st.y = h_p[1];
            *reinterpret_cast<ulonglong2*>(trow + (size_t)t * H_DIM) = st;
        }

        nz = nz_n;
        iv = iv_n;
    }

    // final output row (t = T-1) from the last tanh(h)
    {
        u64 rd0 = dup2(r0), rd1 = dup2(r1), rd2 = dup2(r2), rd3 = dup2(r3);
        u64 qa = mul2(rd0, wo01_p[0]);
        u64 qb = mul2(rd1, wo01_p[1]);
        qa = fma2(rd2, wo01_p[2], qa);
        qb = fma2(rd3, wo01_p[3], qb);
        u64 qacc = add2(qa, qb);
        float a0, a1; unpack2(qacc, a0, a1);
        float d = warp_reduce4(a0, a1, 0.f, 0.f, lane);
        if (lane < 2) pqbuf[lane * 16 + wid] = d;
        __syncthreads();
        if (wid == 0) {
            float v = half_reduce16(pqbuf[lane]);   // lanes 0-15: q0, 16-31: q1
            if (lane == 0)  orow[(T_DIM - 1) * O_DIM + 0] = v;
            if (lane == 16) orow[(T_DIM - 1) * O_DIM + 1] = v;
        }
    }
}

// ---------------- launcher ----------------
extern "C" void kernel_launch(void* const* d_in, const int* in_sizes, int n_in,
                              void* d_out, int out_size) {
    const float* input = (const float*)d_in[0];   // (B,T,I)
    const float* noise = (const float*)d_in[1];   // (B,T,H)
    const float* gb    = (const float*)d_in[2];   // (GB,H)
    const float* sup   = (const float*)d_in[3];   // (S,H)
    const float* wi_w  = (const float*)d_in[4];   // (I,S,GB)
    const float* m_w   = (const float*)d_in[5];   // (R,S,GB)
    const float* n_w   = (const float*)d_in[6];   // (R,S,GB)
    const float* wo_w  = (const float*)d_in[7];   // (O,S,GB)
    const float* wi_b  = (const float*)d_in[8];   // (I,S)
    const float* m_b   = (const float*)d_in[9];   // (R,S)
    const float* n_b   = (const float*)d_in[10];  // (R,S)
    const float* h0_w  = (const float*)d_in[11];  // (S,GB)

    float* out  = (float*)d_out;                                   // (B,T,O)
    float* traj = (float*)d_out + (size_t)B_DIM * T_DIM * O_DIM;   // (B,T,H)

    proxy_kernel<<<(H_DIM + 255) / 256, 256>>>(gb, sup, wi_w, m_w, n_w, wo_w,
                                               wi_b, m_b, n_b, h0_w);
    rnn_kernel<<<B_DIM, NTHREADS>>>(input, noise, out, traj);
}